// round 12
// baseline (speedup 1.0000x reference)
#include <cuda_runtime.h>
#include <cstdint>
#include <cstddef>

// Problem constants
#define EN    1000000
#define NN    100000
#define EORI  200000
#define DD    128
#define RR    32
#define HH    128
#define NRELC 200
#define L2E   1.4426950408889634f

#define NT    7813          // ceil(EN/128)
#define GRID1 148

#define AS_STRIDE 132       // floats; conflict-free A-fragment LDS
#define BS_STRIDE 136       // floats; [n][perm(k)] rows

// smem offsets (uint32 units)
#define BS_OFF   0
#define AS_OFF   (128 * BS_STRIDE)                    // 17408
#define ABUF_U32 (128 * AS_STRIDE)                    // 16896
#define STAT_OFF (AS_OFF + 2 * ABUF_U32)              // 51200
#define STG_OFF  (STAT_OFF + 256)                     // 51456
#define SMEM_U32 (STG_OFF + 16 * 320)                 // 56576 -> 226304 B

// ---------------- scratch globals ----------------
__device__ float g_h[(size_t)EN * HH];   // 512 MB pre-BN activations
__device__ float g_w[EN];                // exp(w) per edge
__device__ float g_sum[HH];
__device__ float g_sumsq[HH];
__device__ float g_nsum[NN];             // per-node softmax denominator
__device__ unsigned char g_flag[EN];     // is-original-edge flag
__device__ float g_prec[NRELC * HH];

// ---------------- helpers ----------------
__device__ __forceinline__ uint32_t tf32u(float x) {
    uint32_t o; asm("cvt.rna.tf32.f32 %0, %1;" : "=r"(o) : "f"(x)); return o;
}
__device__ __forceinline__ void mma_tf32(float c[4], const uint32_t a[4],
                                         const uint32_t b[2]) {
    asm volatile(
        "mma.sync.aligned.m16n8k8.row.col.f32.tf32.tf32.f32 "
        "{%0,%1,%2,%3}, {%4,%5,%6,%7}, {%8,%9}, {%0,%1,%2,%3};"
        : "+f"(c[0]), "+f"(c[1]), "+f"(c[2]), "+f"(c[3])
        : "r"(a[0]), "r"(a[1]), "r"(a[2]), "r"(a[3]), "r"(b[0]), "r"(b[1]));
}
// pack k and k+4 adjacent: one LDS.64 per B fragment
__device__ __forceinline__ int permk(int k) {
    return (k & ~7) | ((k & 3) << 1) | ((k >> 2) & 1);
}

// ---------------- setup kernels ----------------
__global__ void k_setup(const float* __restrict__ rel,
                        const float* __restrict__ W0,
                        const float* __restrict__ b0) {
    int i = blockIdx.x * blockDim.x + threadIdx.x;
    if (i < HH) { g_sum[i] = 0.f; g_sumsq[i] = 0.f; }
    if (i < NN) g_nsum[i] = 0.f;
    if (i < EN) g_flag[i] = 0;
    if (i < NRELC * HH) {
        int r = i / HH, c = i % HH;
        float s = b0[c];
#pragma unroll
        for (int k = 0; k < RR; k++)
            s = fmaf(rel[r * RR + k], W0[(DD + k) * HH + c], s);
        g_prec[i] = s;
    }
}
__global__ void k_flag(const int* __restrict__ ori) {
    int i = blockIdx.x * blockDim.x + threadIdx.x;
    if (i < EORI) g_flag[ori[i]] = 1;
}

// ---------------- pass1 ------------------------------------------------------
// Persistent 148 x 512 (16 warps). Tile = 128 edges x 128 ch, K = 128.
// Warp grid 4(m) x 4(n); warp tile 32x32 via m16n8k8 tf32.
// Order per iteration: sync -> MMA(Ab) -> epilogue(t) -> produce(t+GRID -> An).
// acc is dead during produce, allowing deep LDG batching (MLP 8).

__device__ __forceinline__ void produce128(uint32_t* __restrict__ As,
                                           const float* __restrict__ nf,
                                           const int* __restrict__ rowv,
                                           const int* __restrict__ colv,
                                           int tile, int wid, int lane) {
    const int e0 = tile * 128 + wid * 8;
    int idx = 0;
    {
        int q = e0 + (lane & 7);
        q = (q < EN) ? q : (EN - 1);
        if (lane < 16) idx = (lane < 8) ? rowv[q] : colv[q];
    }
#pragma unroll
    for (int half = 0; half < 2; half++) {
        float4 av[4], bv[4];
#pragma unroll
        for (int i = 0; i < 4; i++) {
            const int rn = __shfl_sync(0xffffffffu, idx, half * 4 + i);
            const int cn = __shfl_sync(0xffffffffu, idx, half * 4 + i + 8);
            av[i] = *(const float4*)(nf + (size_t)rn * DD + lane * 4);
            bv[i] = *(const float4*)(nf + (size_t)cn * DD + lane * 4);
        }
#pragma unroll
        for (int i = 0; i < 4; i++) {
            uint4 s;
            s.x = tf32u(exp2f(-L2E * fabsf(av[i].x - bv[i].x)));
            s.y = tf32u(exp2f(-L2E * fabsf(av[i].y - bv[i].y)));
            s.z = tf32u(exp2f(-L2E * fabsf(av[i].z - bv[i].z)));
            s.w = tf32u(exp2f(-L2E * fabsf(av[i].w - bv[i].w)));
            *(uint4*)(As + (wid * 8 + half * 4 + i) * AS_STRIDE + lane * 4) = s;
        }
    }
}

__global__ __launch_bounds__(512, 1) void k_pass1(
    const float* __restrict__ nf,
    const float* __restrict__ W0,
    const int* __restrict__ rowv,
    const int* __restrict__ colv,
    const int* __restrict__ etype) {
    extern __shared__ uint32_t sm[];
    uint32_t* Bs = sm + BS_OFF;              // [128 n][BS_STRIDE perm-k]
    uint32_t* As0 = sm + AS_OFF;             // [128 m][AS_STRIDE k] x2
    uint32_t* As1 = As0 + ABUF_U32;
    float* ssum = (float*)(sm + STAT_OFF);
    float* ssq  = ssum + 128;

    const int tid = threadIdx.x;
    const int wid = tid >> 5, lane = tid & 31;
    const int gid = lane >> 2, tg = lane & 3;
    const int wm = wid >> 2, wn = wid & 3;
    const int m0 = wm * 32, n0 = wn * 32;
    float2* stg = (float2*)(sm + STG_OFF) + wid * 160;  // 8 rows x 20 float2

    // B = W0[:128,:] tf32 bits, [n][perm(k)]
    for (int i = tid; i < 128 * 128; i += 512) {
        int k = i >> 7, n = i & 127;
        Bs[n * BS_STRIDE + permk(k)] = tf32u(W0[i]);
    }
    if (tid < HH) { ssum[tid] = 0.f; ssq[tid] = 0.f; }

    // per-thread BN accumulators; col(nt,h) = n0 + nt*8 + tg*2 + h
    float ps[8], pq[8];
#pragma unroll
    for (int i = 0; i < 8; i++) { ps[i] = 0.f; pq[i] = 0.f; }

    // prologue: produce first tile into As0
    produce128(As0, nf, rowv, colv, blockIdx.x, wid, lane);

    int it = 0;
    for (int tile = blockIdx.x; tile < NT; tile += GRID1, it++) {
        uint32_t* Ab = (it & 1) ? As1 : As0;
        uint32_t* An = (it & 1) ? As0 : As1;
        __syncthreads();   // Ab fully produced; all reads of An's old data done

        // prefetch etype for this warp's 4 epilogue chunks (hides under MMA)
        int et4[4];
#pragma unroll
        for (int q = 0; q < 4; q++) {
            const int row = m0 + (q >> 1) * 16 + (q & 1) * 8 + gid;
            const int e = tile * 128 + row;
            et4[q] = (e < EN) ? etype[e] : 0;
        }

        // ---- MMA: 2 m-tiles x 4 n-tiles x 16 k-tiles ----
        float acc[2][4][4];
#pragma unroll
        for (int mt = 0; mt < 2; mt++)
#pragma unroll
            for (int nt = 0; nt < 4; nt++)
#pragma unroll
                for (int r = 0; r < 4; r++) acc[mt][nt][r] = 0.f;

#pragma unroll
        for (int kt = 0; kt < 16; kt++) {
            const int k0 = kt * 8;
            uint32_t afr[2][4];
#pragma unroll
            for (int mt = 0; mt < 2; mt++) {
                const uint32_t* ab = Ab + (m0 + mt * 16 + gid) * AS_STRIDE + k0 + tg;
                afr[mt][0] = ab[0];
                afr[mt][1] = ab[8 * AS_STRIDE];
                afr[mt][2] = ab[4];
                afr[mt][3] = ab[8 * AS_STRIDE + 4];
            }
            uint32_t bfr[4][2];
#pragma unroll
            for (int nt = 0; nt < 4; nt++) {
                uint2 bb = *(const uint2*)(Bs + (n0 + nt * 8 + gid) * BS_STRIDE
                                           + k0 + tg * 2);
                bfr[nt][0] = bb.x;
                bfr[nt][1] = bb.y;
            }
#pragma unroll
            for (int mt = 0; mt < 2; mt++)
#pragma unroll
                for (int nt = 0; nt < 4; nt++)
                    mma_tf32(acc[mt][nt], afr[mt], bfr[nt]);
        }

        // ---- epilogue: 4 chunks of 8 rows, staged, coalesced STG.128 ----
#pragma unroll
        for (int mt = 0; mt < 2; mt++) {
#pragma unroll
            for (int rr = 0; rr < 2; rr++) {
                const int rbase = tile * 128 + m0 + mt * 16 + rr * 8;
                const bool valid = (rbase + gid) < EN;
                if (valid) {
                    const int et = et4[mt * 2 + rr];
                    const float2* prow = (const float2*)(g_prec + et * HH);
#pragma unroll
                    for (int nt = 0; nt < 4; nt++) {
                        const int c2g = (n0 + nt * 8 + tg * 2) >> 1;
                        float2 p = prow[c2g];
                        float v0 = acc[mt][nt][rr * 2 + 0] + p.x;
                        float v1 = acc[mt][nt][rr * 2 + 1] + p.y;
                        stg[gid * 20 + nt * 4 + tg] = make_float2(v0, v1);
                        ps[nt * 2 + 0] += v0; pq[nt * 2 + 0] = fmaf(v0, v0, pq[nt * 2 + 0]);
                        ps[nt * 2 + 1] += v1; pq[nt * 2 + 1] = fmaf(v1, v1, pq[nt * 2 + 1]);
                    }
                }
                __syncwarp();
#pragma unroll
                for (int s = 0; s < 2; s++) {
                    const int r = (lane >> 3) + s * 4;     // local row 0..7
                    const int c = lane & 7;                // float4 index
                    const int e = rbase + r;
                    if (e < EN) {
                        float4 v = *(const float4*)((const float*)stg + r * 40 + c * 4);
                        __stcs((float4*)(g_h + (size_t)e * HH + n0 + c * 4), v);
                    }
                }
                __syncwarp();
            }
        }

        // ---- produce NEXT tile into the other buffer (acc dead; deep MLP) ----
        if (tile + GRID1 < NT)
            produce128(An, nf, rowv, colv, tile + GRID1, wid, lane);
    }

    // ---- final BN stat reduction: regs -> smem -> global ----
    __syncthreads();
#pragma unroll
    for (int nt = 0; nt < 4; nt++) {
#pragma unroll
        for (int h = 0; h < 2; h++) {
            const int col = n0 + nt * 8 + tg * 2 + h;
            atomicAdd(&ssum[col], ps[nt * 2 + h]);
            atomicAdd(&ssq[col], pq[nt * 2 + h]);
        }
    }
    __syncthreads();
    if (tid < HH) {
        atomicAdd(&g_sum[tid], ssum[tid]);
        atomicAdd(&g_sumsq[tid], ssq[tid]);
    }
}

// ---------------- pass3: BN params in-block, w, blend, exp, node sum ----------
// Softmax shift-invariance removes the segment-max pass; BN-bounded logits
// keep exp2f in f32 range.
__global__ __launch_bounds__(256) void k_pass3(const int* __restrict__ colv,
                                               const float* __restrict__ W1,
                                               const float* __restrict__ b1,
                                               const float* __restrict__ gamma,
                                               const float* __restrict__ beta) {
    __shared__ float sgi[HH], ssh[HH];
    int tidb = threadIdx.x;
    if (tidb < HH) {
        float mu = g_sum[tidb] * (1.0f / EN);
        float var = g_sumsq[tidb] * (1.0f / EN) - mu * mu;
        float gi = gamma[tidb] * rsqrtf(var + 1e-5f);
        sgi[tidb] = gi;
        ssh[tidb] = beta[tidb] - mu * gi;
    }
    __syncthreads();

    int lane = tidb & 31;
    int warp = (blockIdx.x * blockDim.x + tidb) >> 5;
    int nwarp = (gridDim.x * blockDim.x) >> 5;
    float4 gi = *(const float4*)(sgi + lane * 4);
    float4 sh = *(const float4*)(ssh + lane * 4);
    float4 w1 = *(const float4*)(W1 + lane * 4);
    float b1v = b1[0];
    for (int e = warp; e < EN; e += nwarp) {
        float4 h = __ldcs((const float4*)(g_h + (size_t)e * HH + lane * 4));
        float t, l, s;
        t = fmaf(h.x, gi.x, sh.x); l = fmaxf(t, 0.f) + 0.01f * fminf(t, 0.f); s = l * w1.x;
        t = fmaf(h.y, gi.y, sh.y); l = fmaxf(t, 0.f) + 0.01f * fminf(t, 0.f); s = fmaf(l, w1.y, s);
        t = fmaf(h.z, gi.z, sh.z); l = fmaxf(t, 0.f) + 0.01f * fminf(t, 0.f); s = fmaf(l, w1.z, s);
        t = fmaf(h.w, gi.w, sh.w); l = fmaxf(t, 0.f) + 0.01f * fminf(t, 0.f); s = fmaf(l, w1.w, s);
        s += __shfl_xor_sync(0xffffffffu, s, 16);
        s += __shfl_xor_sync(0xffffffffu, s, 8);
        s += __shfl_xor_sync(0xffffffffu, s, 4);
        s += __shfl_xor_sync(0xffffffffu, s, 2);
        s += __shfl_xor_sync(0xffffffffu, s, 1);
        if (lane == 0) {
            float wv = s + b1v;
            if (g_flag[e]) wv = 0.5f * wv + 0.5f;
            float ev = exp2f(wv * L2E);
            g_w[e] = ev;
            atomicAdd(&g_nsum[colv[e]], ev);
        }
    }
}

__global__ void k_pass5(const int* __restrict__ colv, float* __restrict__ out) {
    int e = blockIdx.x * blockDim.x + threadIdx.x;
    if (e >= EN) return;
    int cn = colv[e];
    float o = __ldcs(&g_w[e]) / g_nsum[cn];
    out[e] = (o > 1e-4f) ? o : 0.f;
}

// ---------------- launch ----------------
extern "C" void kernel_launch(void* const* d_in, const int* in_sizes, int n_in,
                              void* d_out, int out_size) {
    const float* n_feat  = (const float*)d_in[0];
    const float* rel_emb = (const float*)d_in[1];
    const float* W0      = (const float*)d_in[2];
    const float* b0      = (const float*)d_in[3];
    const float* gamma   = (const float*)d_in[4];
    const float* beta    = (const float*)d_in[5];
    const float* W1      = (const float*)d_in[6];
    const float* b1      = (const float*)d_in[7];
    const int*   rowv    = (const int*)d_in[8];
    const int*   colv    = (const int*)d_in[9];
    const int*   etype   = (const int*)d_in[10];
    const int*   ori     = (const int*)d_in[11];
    float* out = (float*)d_out;

    const int smem1 = SMEM_U32 * 4;   // 226,304 B
    static bool attr_done = false;
    if (!attr_done) {
        cudaFuncSetAttribute(k_pass1, cudaFuncAttributeMaxDynamicSharedMemorySize, smem1);
        attr_done = true;
    }

    k_setup<<<(EN + 255) / 256, 256>>>(rel_emb, W0, b0);
    k_flag<<<(EORI + 255) / 256, 256>>>(ori);
    k_pass1<<<GRID1, 512, smem1>>>(n_feat, W0, rowv, colv, etype);
    k_pass3<<<2048, 256>>>(colv, W1, b1, gamma, beta);
    k_pass5<<<(EN + 255) / 256, 256>>>(colv, out);
}

// round 13
// speedup vs baseline: 1.0876x; 1.0876x over previous
#include <cuda_runtime.h>
#include <cstdint>
#include <cstddef>

// Problem constants
#define EN    1000000
#define NN    100000
#define EORI  200000
#define DD    128
#define RR    32
#define HH    128
#define NRELC 200
#define L2E   1.4426950408889634f

#define NT    7813          // ceil(EN/128)
#define GRID1 148

#define AS_STRIDE 132       // floats; conflict-free A-fragment LDS
#define BS_STRIDE 136       // floats; [n][perm(k)] rows

// smem offsets (uint32 units)
#define BS_OFF   0
#define AS_OFF   (128 * BS_STRIDE)                    // 17408
#define ABUF_U32 (128 * AS_STRIDE)                    // 16896
#define STAT_OFF (AS_OFF + 2 * ABUF_U32)              // 51200
#define STG_OFF  (STAT_OFF + 256)                     // 51456
#define SMEM_U32 (STG_OFF + 16 * 320)                 // 56576 -> 226304 B

// ---------------- scratch globals ----------------
__device__ float g_h[(size_t)EN * HH];   // 512 MB pre-BN activations
__device__ float g_w[EN];                // exp(w) per edge
__device__ float g_sum[HH];
__device__ float g_sumsq[HH];
__device__ float g_nsum[NN];             // per-node softmax denominator
__device__ unsigned char g_flag[EN];     // is-original-edge flag
__device__ float g_prec[NRELC * HH];

// ---------------- helpers ----------------
__device__ __forceinline__ uint32_t tf32u(float x) {
    uint32_t o; asm("cvt.rna.tf32.f32 %0, %1;" : "=r"(o) : "f"(x)); return o;
}
__device__ __forceinline__ void mma_tf32(float c[4], const uint32_t a[4],
                                         const uint32_t b[2]) {
    asm volatile(
        "mma.sync.aligned.m16n8k8.row.col.f32.tf32.tf32.f32 "
        "{%0,%1,%2,%3}, {%4,%5,%6,%7}, {%8,%9}, {%0,%1,%2,%3};"
        : "+f"(c[0]), "+f"(c[1]), "+f"(c[2]), "+f"(c[3])
        : "r"(a[0]), "r"(a[1]), "r"(a[2]), "r"(a[3]), "r"(b[0]), "r"(b[1]));
}
// pack k and k+4 adjacent: one LDS.64 per B fragment
__device__ __forceinline__ int permk(int k) {
    return (k & ~7) | ((k & 3) << 1) | ((k >> 2) & 1);
}

// ---------------- setup kernels ----------------
__global__ void k_setup(const float* __restrict__ rel,
                        const float* __restrict__ W0,
                        const float* __restrict__ b0) {
    int i = blockIdx.x * blockDim.x + threadIdx.x;
    if (i < HH) { g_sum[i] = 0.f; g_sumsq[i] = 0.f; }
    if (i < NN) g_nsum[i] = 0.f;
    if (i < EN) g_flag[i] = 0;
    if (i < NRELC * HH) {
        int r = i / HH, c = i % HH;
        float s = b0[c];
#pragma unroll
        for (int k = 0; k < RR; k++)
            s = fmaf(rel[r * RR + k], W0[(DD + k) * HH + c], s);
        g_prec[i] = s;
    }
}
__global__ void k_flag(const int* __restrict__ ori) {
    int i = blockIdx.x * blockDim.x + threadIdx.x;
    if (i < EORI) g_flag[ori[i]] = 1;
}

// ---------------- pass1 ------------------------------------------------------
// Persistent 148 x 512 (16 warps). Tile = 128 edges x 128 ch, K = 128.
// Warp grid 4(m) x 4(n); warp tile 32x32 via m16n8k8 tf32.
// Order (R11, known-good): sync -> MMA(Ab) -> produce(t+GRID -> An) -> epilogue.
// The epilogue behind produce hides produce's LDG latency.

__device__ __forceinline__ void produce128(uint32_t* __restrict__ As,
                                           const float* __restrict__ nf,
                                           const int* __restrict__ rowv,
                                           const int* __restrict__ colv,
                                           int tile, int wid, int lane) {
    const int e0 = tile * 128 + wid * 8;
    int idx = 0;
    {
        int q = e0 + (lane & 7);
        q = (q < EN) ? q : (EN - 1);
        if (lane < 16) idx = (lane < 8) ? rowv[q] : colv[q];
    }
#pragma unroll 2
    for (int i = 0; i < 8; i++) {
        const int rn = __shfl_sync(0xffffffffu, idx, i);
        const int cn = __shfl_sync(0xffffffffu, idx, i + 8);
        float4 a = *(const float4*)(nf + (size_t)rn * DD + lane * 4);
        float4 b = *(const float4*)(nf + (size_t)cn * DD + lane * 4);
        uint4 s;
        s.x = tf32u(exp2f(-L2E * fabsf(a.x - b.x)));
        s.y = tf32u(exp2f(-L2E * fabsf(a.y - b.y)));
        s.z = tf32u(exp2f(-L2E * fabsf(a.z - b.z)));
        s.w = tf32u(exp2f(-L2E * fabsf(a.w - b.w)));
        *(uint4*)(As + (wid * 8 + i) * AS_STRIDE + lane * 4) = s;
    }
}

__global__ __launch_bounds__(512, 1) void k_pass1(
    const float* __restrict__ nf,
    const float* __restrict__ W0,
    const int* __restrict__ rowv,
    const int* __restrict__ colv,
    const int* __restrict__ etype) {
    extern __shared__ uint32_t sm[];
    uint32_t* Bs = sm + BS_OFF;              // [128 n][BS_STRIDE perm-k]
    uint32_t* As0 = sm + AS_OFF;             // [128 m][AS_STRIDE k] x2
    uint32_t* As1 = As0 + ABUF_U32;
    float* ssum = (float*)(sm + STAT_OFF);
    float* ssq  = ssum + 128;

    const int tid = threadIdx.x;
    const int wid = tid >> 5, lane = tid & 31;
    const int gid = lane >> 2, tg = lane & 3;
    const int wm = wid >> 2, wn = wid & 3;
    const int m0 = wm * 32, n0 = wn * 32;
    float2* stg = (float2*)(sm + STG_OFF) + wid * 160;  // 8 rows x 20 float2

    // B = W0[:128,:] tf32 bits, [n][perm(k)]
    for (int i = tid; i < 128 * 128; i += 512) {
        int k = i >> 7, n = i & 127;
        Bs[n * BS_STRIDE + permk(k)] = tf32u(W0[i]);
    }
    if (tid < HH) { ssum[tid] = 0.f; ssq[tid] = 0.f; }

    // per-thread BN accumulators; col(nt,h) = n0 + nt*8 + tg*2 + h
    float ps[8], pq[8];
#pragma unroll
    for (int i = 0; i < 8; i++) { ps[i] = 0.f; pq[i] = 0.f; }

    // prologue: produce first tile into As0
    produce128(As0, nf, rowv, colv, blockIdx.x, wid, lane);

    int it = 0;
    for (int tile = blockIdx.x; tile < NT; tile += GRID1, it++) {
        uint32_t* Ab = (it & 1) ? As1 : As0;
        uint32_t* An = (it & 1) ? As0 : As1;
        __syncthreads();   // Ab fully produced; prior iter fully done

        // prefetch etype for this warp's 4 epilogue chunks (hides under MMA)
        int et4[4];
#pragma unroll
        for (int q = 0; q < 4; q++) {
            const int row = m0 + (q >> 1) * 16 + (q & 1) * 8 + gid;
            const int e = tile * 128 + row;
            et4[q] = (e < EN) ? etype[e] : 0;
        }

        // ---- MMA: 2 m-tiles x 4 n-tiles x 16 k-tiles ----
        float acc[2][4][4];
#pragma unroll
        for (int mt = 0; mt < 2; mt++)
#pragma unroll
            for (int nt = 0; nt < 4; nt++)
#pragma unroll
                for (int r = 0; r < 4; r++) acc[mt][nt][r] = 0.f;

#pragma unroll
        for (int kt = 0; kt < 16; kt++) {
            const int k0 = kt * 8;
            uint32_t afr[2][4];
#pragma unroll
            for (int mt = 0; mt < 2; mt++) {
                const uint32_t* ab = Ab + (m0 + mt * 16 + gid) * AS_STRIDE + k0 + tg;
                afr[mt][0] = ab[0];
                afr[mt][1] = ab[8 * AS_STRIDE];
                afr[mt][2] = ab[4];
                afr[mt][3] = ab[8 * AS_STRIDE + 4];
            }
            uint32_t bfr[4][2];
#pragma unroll
            for (int nt = 0; nt < 4; nt++) {
                uint2 bb = *(const uint2*)(Bs + (n0 + nt * 8 + gid) * BS_STRIDE
                                           + k0 + tg * 2);
                bfr[nt][0] = bb.x;
                bfr[nt][1] = bb.y;
            }
#pragma unroll
            for (int mt = 0; mt < 2; mt++)
#pragma unroll
                for (int nt = 0; nt < 4; nt++)
                    mma_tf32(acc[mt][nt], afr[mt], bfr[nt]);
        }

        // ---- produce NEXT tile into the other buffer (no barrier needed) ----
        if (tile + GRID1 < NT)
            produce128(An, nf, rowv, colv, tile + GRID1, wid, lane);

        // ---- epilogue: 4 chunks of 8 rows, staged, coalesced STG.128 ----
#pragma unroll
        for (int mt = 0; mt < 2; mt++) {
#pragma unroll
            for (int rr = 0; rr < 2; rr++) {
                const int rbase = tile * 128 + m0 + mt * 16 + rr * 8;
                const bool valid = (rbase + gid) < EN;
                if (valid) {
                    const int et = et4[mt * 2 + rr];
                    const float2* prow = (const float2*)(g_prec + et * HH);
#pragma unroll
                    for (int nt = 0; nt < 4; nt++) {
                        const int c2g = (n0 + nt * 8 + tg * 2) >> 1;
                        float2 p = prow[c2g];
                        float v0 = acc[mt][nt][rr * 2 + 0] + p.x;
                        float v1 = acc[mt][nt][rr * 2 + 1] + p.y;
                        stg[gid * 20 + nt * 4 + tg] = make_float2(v0, v1);
                        ps[nt * 2 + 0] += v0; pq[nt * 2 + 0] = fmaf(v0, v0, pq[nt * 2 + 0]);
                        ps[nt * 2 + 1] += v1; pq[nt * 2 + 1] = fmaf(v1, v1, pq[nt * 2 + 1]);
                    }
                }
                __syncwarp();
#pragma unroll
                for (int s = 0; s < 2; s++) {
                    const int r = (lane >> 3) + s * 4;     // local row 0..7
                    const int c = lane & 7;                // float4 index
                    const int e = rbase + r;
                    if (e < EN) {
                        float4 v = *(const float4*)((const float*)stg + r * 40 + c * 4);
                        __stcs((float4*)(g_h + (size_t)e * HH + n0 + c * 4), v);
                    }
                }
                __syncwarp();
            }
        }
    }

    // ---- final BN stat reduction: regs -> smem -> global ----
    __syncthreads();
#pragma unroll
    for (int nt = 0; nt < 4; nt++) {
#pragma unroll
        for (int h = 0; h < 2; h++) {
            const int col = n0 + nt * 8 + tg * 2 + h;
            atomicAdd(&ssum[col], ps[nt * 2 + h]);
            atomicAdd(&ssq[col], pq[nt * 2 + h]);
        }
    }
    __syncthreads();
    if (tid < HH) {
        atomicAdd(&g_sum[tid], ssum[tid]);
        atomicAdd(&g_sumsq[tid], ssq[tid]);
    }
}

// ---------------- pass3: BN params in-block, 4 edges/warp-iter ----------------
// Softmax shift-invariance removes the segment-max pass.
__global__ __launch_bounds__(256) void k_pass3(const int* __restrict__ colv,
                                               const float* __restrict__ W1,
                                               const float* __restrict__ b1,
                                               const float* __restrict__ gamma,
                                               const float* __restrict__ beta) {
    __shared__ float sgi[HH], ssh[HH];
    int tidb = threadIdx.x;
    if (tidb < HH) {
        float mu = g_sum[tidb] * (1.0f / EN);
        float var = g_sumsq[tidb] * (1.0f / EN) - mu * mu;
        float gi = gamma[tidb] * rsqrtf(var + 1e-5f);
        sgi[tidb] = gi;
        ssh[tidb] = beta[tidb] - mu * gi;
    }
    __syncthreads();

    const int lane = tidb & 31;
    const int warp = (blockIdx.x * blockDim.x + tidb) >> 5;
    const int nwarp = (gridDim.x * blockDim.x) >> 5;
    const float4 gi = *(const float4*)(sgi + lane * 4);
    const float4 sh = *(const float4*)(ssh + lane * 4);
    const float4 w1 = *(const float4*)(W1 + lane * 4);
    const float b1v = b1[0];

    for (int e = warp * 4; e < EN; e += nwarp * 4) {     // EN % 4 == 0
        // batch 4 row loads (MLP 4 per warp)
        float4 h[4];
#pragma unroll
        for (int j = 0; j < 4; j++)
            h[j] = __ldcs((const float4*)(g_h + (size_t)(e + j) * HH + lane * 4));
        int4 cn4;
        if (lane == 0) cn4 = *(const int4*)(colv + e);

        float sdot[4];
#pragma unroll
        for (int j = 0; j < 4; j++) {
            float t, l, s;
            t = fmaf(h[j].x, gi.x, sh.x); l = fmaxf(t, 0.f) + 0.01f * fminf(t, 0.f); s = l * w1.x;
            t = fmaf(h[j].y, gi.y, sh.y); l = fmaxf(t, 0.f) + 0.01f * fminf(t, 0.f); s = fmaf(l, w1.y, s);
            t = fmaf(h[j].z, gi.z, sh.z); l = fmaxf(t, 0.f) + 0.01f * fminf(t, 0.f); s = fmaf(l, w1.z, s);
            t = fmaf(h[j].w, gi.w, sh.w); l = fmaxf(t, 0.f) + 0.01f * fminf(t, 0.f); s = fmaf(l, w1.w, s);
            sdot[j] = s;
        }
        // 4 independent reduce chains interleave in the scheduler
#pragma unroll
        for (int j = 0; j < 4; j++) {
            sdot[j] += __shfl_xor_sync(0xffffffffu, sdot[j], 16);
            sdot[j] += __shfl_xor_sync(0xffffffffu, sdot[j], 8);
            sdot[j] += __shfl_xor_sync(0xffffffffu, sdot[j], 4);
            sdot[j] += __shfl_xor_sync(0xffffffffu, sdot[j], 2);
            sdot[j] += __shfl_xor_sync(0xffffffffu, sdot[j], 1);
        }
        if (lane == 0) {
            float ev4[4];
            const int cns[4] = {cn4.x, cn4.y, cn4.z, cn4.w};
#pragma unroll
            for (int j = 0; j < 4; j++) {
                float wv = sdot[j] + b1v;
                if (g_flag[e + j]) wv = 0.5f * wv + 0.5f;
                ev4[j] = exp2f(wv * L2E);
            }
            *(float4*)(g_w + e) = make_float4(ev4[0], ev4[1], ev4[2], ev4[3]);
#pragma unroll
            for (int j = 0; j < 4; j++)
                atomicAdd(&g_nsum[cns[j]], ev4[j]);
        }
    }
}

// ---------------- pass5: vectorized x4 ----------------
__global__ void k_pass5(const int* __restrict__ colv, float* __restrict__ out) {
    int e = (blockIdx.x * blockDim.x + threadIdx.x) * 4;
    if (e >= EN) return;
    float4 w4 = *(const float4*)(g_w + e);
    int4 c4 = *(const int4*)(colv + e);
    float4 o;
    o.x = w4.x / g_nsum[c4.x];
    o.y = w4.y / g_nsum[c4.y];
    o.z = w4.z / g_nsum[c4.z];
    o.w = w4.w / g_nsum[c4.w];
    o.x = (o.x > 1e-4f) ? o.x : 0.f;
    o.y = (o.y > 1e-4f) ? o.y : 0.f;
    o.z = (o.z > 1e-4f) ? o.z : 0.f;
    o.w = (o.w > 1e-4f) ? o.w : 0.f;
    *(float4*)(out + e) = o;
}

// ---------------- launch ----------------
extern "C" void kernel_launch(void* const* d_in, const int* in_sizes, int n_in,
                              void* d_out, int out_size) {
    const float* n_feat  = (const float*)d_in[0];
    const float* rel_emb = (const float*)d_in[1];
    const float* W0      = (const float*)d_in[2];
    const float* b0      = (const float*)d_in[3];
    const float* gamma   = (const float*)d_in[4];
    const float* beta    = (const float*)d_in[5];
    const float* W1      = (const float*)d_in[6];
    const float* b1      = (const float*)d_in[7];
    const int*   rowv    = (const int*)d_in[8];
    const int*   colv    = (const int*)d_in[9];
    const int*   etype   = (const int*)d_in[10];
    const int*   ori     = (const int*)d_in[11];
    float* out = (float*)d_out;

    const int smem1 = SMEM_U32 * 4;   // 226,304 B
    static bool attr_done = false;
    if (!attr_done) {
        cudaFuncSetAttribute(k_pass1, cudaFuncAttributeMaxDynamicSharedMemorySize, smem1);
        attr_done = true;
    }

    k_setup<<<(EN + 255) / 256, 256>>>(rel_emb, W0, b0);
    k_flag<<<(EORI + 255) / 256, 256>>>(ori);
    k_pass1<<<GRID1, 512, smem1>>>(n_feat, W0, rowv, colv, etype);
    k_pass3<<<2048, 256>>>(colv, W1, b1, gamma, beta);
    k_pass5<<<(EN / 4 + 255) / 256, 256>>>(colv, out);
}